// round 2
// baseline (speedup 1.0000x reference)
#include <cuda_runtime.h>

#define NN 100000
#define EE 1600000

// ---------------- device scratch (allocated at module load, allowed) ----------------
__device__ float g_x[NN * 128];
__device__ float g_h[NN * 128];
__device__ float g_z[NN * 128];
__device__ float g_als[NN * 4];
__device__ float g_ald[NN * 4];
__device__ int   g_deg[NN];
__device__ int   g_ptr[NN + 1];
__device__ int   g_pos[NN];
__device__ int   g_csrc[EE + NN];
__device__ int   g_part[128];
__device__ int   g_partex[128];

__device__ __forceinline__ float lrelu(float v, float s) { return v > 0.f ? v : s * v; }

// ---------------- CSR build (dst-major), shared by both GAT layers ----------------
__global__ void k_init_deg() {
    int i = blockIdx.x * blockDim.x + threadIdx.x;
    if (i < NN) g_deg[i] = 1;  // self loop
}

__global__ void k_count(const int* __restrict__ ei) {
    int e = blockIdx.x * blockDim.x + threadIdx.x;
    if (e < EE) atomicAdd(&g_deg[ei[EE + e]], 1);
}

__global__ void k_scan1() {
    __shared__ int sm[1024];
    int t = threadIdx.x;
    int i = blockIdx.x * 1024 + t;
    int v = (i < NN) ? g_deg[i] : 0;
    sm[t] = v; __syncthreads();
    for (int off = 1; off < 1024; off <<= 1) {
        int x = (t >= off) ? sm[t - off] : 0;
        __syncthreads();
        sm[t] += x; __syncthreads();
    }
    if (i < NN) g_ptr[i + 1] = sm[t];
    if (t == 1023) g_part[blockIdx.x] = sm[t];
}

__global__ void k_scan2() {
    __shared__ int sm[128];
    int t = threadIdx.x;
    int v = (t < 98) ? g_part[t] : 0;
    sm[t] = v; __syncthreads();
    for (int off = 1; off < 128; off <<= 1) {
        int x = (t >= off) ? sm[t - off] : 0;
        __syncthreads();
        sm[t] += x; __syncthreads();
    }
    if (t < 98) g_partex[t] = sm[t] - v;
}

__global__ void k_scan3() {
    int t = threadIdx.x;
    int i = blockIdx.x * 1024 + t;
    if (i < NN) {
        int val = g_ptr[i + 1] + g_partex[blockIdx.x];
        g_ptr[i + 1] = val;
        g_pos[i] = val - g_deg[i];
        if (i == 0) g_ptr[0] = 0;
    }
}

__global__ void k_fill(const int* __restrict__ ei) {
    int idx = blockIdx.x * blockDim.x + threadIdx.x;
    if (idx < EE + NN) {
        int s, d;
        if (idx < EE) { s = ei[idx]; d = ei[EE + idx]; }
        else          { s = idx - EE; d = s; }
        int p = atomicAdd(&g_pos[d], 1);
        g_csrc[p] = s;
    }
}

// ---------------- GEMM: A[n,128] @ B[128,128] (+bias, optional leaky 0.01) ----------------
// block: 256 thr, tile 128x128, K chunked by 32. thread tile 8x8 in 4 quadrants.
__global__ __launch_bounds__(256) void k_gemm128(
    const float* __restrict__ A, const float* __restrict__ B,
    const float* __restrict__ bias, float* __restrict__ C, int n, int doLeaky)
{
    __shared__ float As[32][132];
    __shared__ float Bs[32][132];
    int tid = threadIdx.x;
    int m0 = blockIdx.x * 128;
    int tr = tid >> 4, tc = tid & 15;
    float acc[64];
#pragma unroll
    for (int i = 0; i < 64; i++) acc[i] = 0.f;

    for (int kc = 0; kc < 128; kc += 32) {
#pragma unroll
        for (int i = 0; i < 4; i++) {            // A tile 128x32 (store transposed)
            int idx = i * 256 + tid;
            int r = idx >> 3, kq = idx & 7;
            float4 f = make_float4(0.f, 0.f, 0.f, 0.f);
            if (m0 + r < n) f = *(const float4*)&A[(size_t)(m0 + r) * 128 + kc + kq * 4];
            As[kq * 4 + 0][r] = f.x; As[kq * 4 + 1][r] = f.y;
            As[kq * 4 + 2][r] = f.z; As[kq * 4 + 3][r] = f.w;
        }
#pragma unroll
        for (int i = 0; i < 4; i++) {            // B tile 32x128
            int idx = i * 256 + tid;
            int k = idx >> 5, cq = idx & 31;
            float4 f = *(const float4*)&B[(kc + k) * 128 + cq * 4];
            *(float4*)&Bs[k][cq * 4] = f;
        }
        __syncthreads();
#pragma unroll
        for (int k = 0; k < 32; k++) {
            float4 a0 = *(const float4*)&As[k][tr * 4];
            float4 a1 = *(const float4*)&As[k][64 + tr * 4];
            float4 b0 = *(const float4*)&Bs[k][tc * 4];
            float4 b1 = *(const float4*)&Bs[k][64 + tc * 4];
            float ar[8] = {a0.x, a0.y, a0.z, a0.w, a1.x, a1.y, a1.z, a1.w};
            float br[8] = {b0.x, b0.y, b0.z, b0.w, b1.x, b1.y, b1.z, b1.w};
#pragma unroll
            for (int ri = 0; ri < 8; ri++)
#pragma unroll
                for (int ci = 0; ci < 8; ci++)
                    acc[ri * 8 + ci] += ar[ri] * br[ci];
        }
        __syncthreads();
    }

    float bb[8];
#pragma unroll
    for (int ci = 0; ci < 8; ci++) {
        int c = (ci < 4) ? tc * 4 + ci : 64 + tc * 4 + (ci - 4);
        bb[ci] = bias ? bias[c] : 0.f;
    }
#pragma unroll
    for (int ri = 0; ri < 8; ri++) {
        int r = (ri < 4) ? tr * 4 + ri : 64 + tr * 4 + (ri - 4);
        if (m0 + r < n) {
            float4 o0, o1;
            float v;
            v = acc[ri * 8 + 0] + bb[0]; o0.x = doLeaky ? lrelu(v, 0.01f) : v;
            v = acc[ri * 8 + 1] + bb[1]; o0.y = doLeaky ? lrelu(v, 0.01f) : v;
            v = acc[ri * 8 + 2] + bb[2]; o0.z = doLeaky ? lrelu(v, 0.01f) : v;
            v = acc[ri * 8 + 3] + bb[3]; o0.w = doLeaky ? lrelu(v, 0.01f) : v;
            v = acc[ri * 8 + 4] + bb[4]; o1.x = doLeaky ? lrelu(v, 0.01f) : v;
            v = acc[ri * 8 + 5] + bb[5]; o1.y = doLeaky ? lrelu(v, 0.01f) : v;
            v = acc[ri * 8 + 6] + bb[6]; o1.z = doLeaky ? lrelu(v, 0.01f) : v;
            v = acc[ri * 8 + 7] + bb[7]; o1.w = doLeaky ? lrelu(v, 0.01f) : v;
            *(float4*)&C[(size_t)(m0 + r) * 128 + tc * 4] = o0;
            *(float4*)&C[(size_t)(m0 + r) * 128 + 64 + tc * 4] = o1;
        }
    }
}

// ---------------- GEMM: A[n,K] @ B[K,32] (+bias, leaky 0.01), into C[:,colOff..colOff+32) ----------------
// block: 256 thr, tile 256 rows x 32 cols, K chunked by 32. thread tile 8x4.
__global__ __launch_bounds__(256) void k_gemm_enc(
    const float* __restrict__ A, int lda,
    const float* __restrict__ B, const float* __restrict__ bias,
    float* __restrict__ C, int colOff, int n, int K)
{
    __shared__ float As[32][260];
    __shared__ float Bs[32][36];
    int tid = threadIdx.x;
    int m0 = blockIdx.x * 256;
    int tr = tid >> 3, tc = tid & 7;
    float acc[32];
#pragma unroll
    for (int i = 0; i < 32; i++) acc[i] = 0.f;

    for (int kc = 0; kc < K; kc += 32) {
#pragma unroll
        for (int i = 0; i < 8; i++) {            // A tile 256x32 (store transposed)
            int idx = i * 256 + tid;
            int r = idx >> 3, kq = idx & 7;
            float4 f = make_float4(0.f, 0.f, 0.f, 0.f);
            if (m0 + r < n) f = *(const float4*)&A[(size_t)(m0 + r) * lda + kc + kq * 4];
            As[kq * 4 + 0][r] = f.x; As[kq * 4 + 1][r] = f.y;
            As[kq * 4 + 2][r] = f.z; As[kq * 4 + 3][r] = f.w;
        }
        {                                         // B tile 32x32
            int k = tid >> 3, cq = tid & 7;
            float4 f = *(const float4*)&B[(kc + k) * 32 + cq * 4];
            *(float4*)&Bs[k][cq * 4] = f;
        }
        __syncthreads();
#pragma unroll
        for (int k = 0; k < 32; k++) {
            float4 a0 = *(const float4*)&As[k][tr * 4];
            float4 a1 = *(const float4*)&As[k][128 + tr * 4];
            float4 b  = *(const float4*)&Bs[k][tc * 4];
            float ar[8] = {a0.x, a0.y, a0.z, a0.w, a1.x, a1.y, a1.z, a1.w};
            float br[4] = {b.x, b.y, b.z, b.w};
#pragma unroll
            for (int ri = 0; ri < 8; ri++)
#pragma unroll
                for (int ci = 0; ci < 4; ci++)
                    acc[ri * 4 + ci] += ar[ri] * br[ci];
        }
        __syncthreads();
    }

    float bb[4];
#pragma unroll
    for (int ci = 0; ci < 4; ci++) bb[ci] = bias[tc * 4 + ci];
#pragma unroll
    for (int ri = 0; ri < 8; ri++) {
        int r = (ri < 4) ? tr * 4 + ri : 128 + tr * 4 + (ri - 4);
        if (m0 + r < n) {
            float4 o;
            o.x = lrelu(acc[ri * 4 + 0] + bb[0], 0.01f);
            o.y = lrelu(acc[ri * 4 + 1] + bb[1], 0.01f);
            o.z = lrelu(acc[ri * 4 + 2] + bb[2], 0.01f);
            o.w = lrelu(acc[ri * 4 + 3] + bb[3], 0.01f);
            *(float4*)&C[(size_t)(m0 + r) * 128 + colOff + tc * 4] = o;
        }
    }
}

// ---------------- tiny encoders (num_prop 5->32, cat_prop 3->32) ----------------
__global__ void k_small(const float* __restrict__ np_, const float* __restrict__ cp,
                        const float* __restrict__ Wnp, const float* __restrict__ bnp,
                        const float* __restrict__ Wcp, const float* __restrict__ bcp)
{
    int g = blockIdx.x * blockDim.x + threadIdx.x;
    int nID = g >> 5, c = g & 31;
    if (nID >= NN) return;
    float s = bnp[c];
#pragma unroll
    for (int k = 0; k < 5; k++) s += __ldg(&np_[nID * 5 + k]) * Wnp[k * 32 + c];
    g_x[(size_t)nID * 128 + 64 + c] = lrelu(s, 0.01f);
    float s2 = bcp[c];
#pragma unroll
    for (int k = 0; k < 3; k++) s2 += __ldg(&cp[nID * 3 + k]) * Wcp[k * 32 + c];
    g_x[(size_t)nID * 128 + 96 + c] = lrelu(s2, 0.01f);
}

// ---------------- per-node attention logit halves: als/ald ----------------
__global__ void k_al(const float* __restrict__ h, const float* __restrict__ asrc,
                     const float* __restrict__ adst, int n, int H)
{
    int w = (blockIdx.x * blockDim.x + threadIdx.x) >> 5;
    int lane = threadIdx.x & 31;
    if (w >= n) return;
    float ps[4], pd[4];
#pragma unroll
    for (int q = 0; q < 4; q++) {
        float hv = h[(size_t)w * 128 + q * 32 + lane];
        ps[q] = hv * asrc[q * 32 + lane];
        pd[q] = hv * adst[q * 32 + lane];
    }
    if (H == 1) { ps[0] += ps[1] + ps[2] + ps[3]; pd[0] += pd[1] + pd[2] + pd[3]; }
    int QQ = (H == 4) ? 4 : 1;
    for (int q = 0; q < QQ; q++) {
        float s1 = ps[q], s2 = pd[q];
        for (int off = 16; off; off >>= 1) {
            s1 += __shfl_xor_sync(0xffffffffu, s1, off);
            s2 += __shfl_xor_sync(0xffffffffu, s2, off);
        }
        if (lane == 0) { g_als[(size_t)w * H + q] = s1; g_ald[(size_t)w * H + q] = s2; }
    }
}

// ---------------- GAT aggregation: warp per node, CSR gather, two-sweep softmax ----------------
__global__ void k_gat(const float* __restrict__ h, const float* __restrict__ bias,
                      float* __restrict__ out, int n, int H)
{
    int w = (blockIdx.x * blockDim.x + threadIdx.x) >> 5;
    int lane = threadIdx.x & 31;
    if (w >= n) return;
    int beg = g_ptr[w], end = g_ptr[w + 1];
    float aldv = (lane < H) ? g_ald[(size_t)w * H + lane] : 0.f;

    // sweep 1: per-head max (tracked on lanes < H)
    float mx = -1e30f;
    for (int e = beg; e < end; e++) {
        int src = __ldg(&g_csrc[e]);
        if (lane < H) {
            float v = g_als[(size_t)src * H + lane] + aldv;
            v = v > 0.f ? v : 0.2f * v;
            mx = fmaxf(mx, v);
        }
    }

    // sweep 2: weighted aggregation
    float s[4] = {0.f, 0.f, 0.f, 0.f}, acc[4] = {0.f, 0.f, 0.f, 0.f};
    for (int e = beg; e < end; e++) {
        int src = __ldg(&g_csrc[e]);
        float wv = 0.f;
        if (lane < H) {
            float v = g_als[(size_t)src * H + lane] + aldv;
            v = v > 0.f ? v : 0.2f * v;
            wv = __expf(v - mx);
        }
#pragma unroll
        for (int q = 0; q < 4; q++) {
            int hq = (H == 4) ? q : 0;
            float wq = __shfl_sync(0xffffffffu, wv, hq);
            float hv = __ldg(&h[(size_t)src * 128 + q * 32 + lane]);
            s[q] += wq;
            acc[q] += wq * hv;
        }
    }
#pragma unroll
    for (int q = 0; q < 4; q++) {
        int ch = q * 32 + lane;
        out[(size_t)w * 128 + ch] = acc[q] / (s[q] + 1e-16f) + bias[ch];
    }
}

// ---------------- output head: z[n,128] @ W_o2[128,2] + b ----------------
__global__ void k_out(const float* __restrict__ z, const float* __restrict__ W,
                      const float* __restrict__ b, float* __restrict__ out, int n)
{
    int w = (blockIdx.x * blockDim.x + threadIdx.x) >> 5;
    int lane = threadIdx.x & 31;
    if (w >= n) return;
    float p0 = 0.f, p1 = 0.f;
#pragma unroll
    for (int q = 0; q < 4; q++) {
        int ch = q * 32 + lane;
        float zv = z[(size_t)w * 128 + ch];
        p0 += zv * W[ch * 2];
        p1 += zv * W[ch * 2 + 1];
    }
    for (int off = 16; off; off >>= 1) {
        p0 += __shfl_xor_sync(0xffffffffu, p0, off);
        p1 += __shfl_xor_sync(0xffffffffu, p1, off);
    }
    if (lane == 0) { out[2 * w] = p0 + b[0]; out[2 * w + 1] = p1 + b[1]; }
}

// ---------------- launch ----------------
extern "C" void kernel_launch(void* const* d_in, const int* in_sizes, int n_in,
                              void* d_out, int out_size)
{
    const float* des  = (const float*)d_in[0];
    const float* tw   = (const float*)d_in[1];
    const float* np_  = (const float*)d_in[2];
    const float* cp   = (const float*)d_in[3];
    const int*   ei   = (const int*)d_in[4];      // JAX demotes int64 -> int32
    const float* W_des = (const float*)d_in[5];  const float* b_des = (const float*)d_in[6];
    const float* W_tw  = (const float*)d_in[7];  const float* b_tw  = (const float*)d_in[8];
    const float* W_np  = (const float*)d_in[9];  const float* b_np  = (const float*)d_in[10];
    const float* W_cp  = (const float*)d_in[11]; const float* b_cp  = (const float*)d_in[12];
    const float* W_in  = (const float*)d_in[13]; const float* b_in  = (const float*)d_in[14];
    const float* g1W   = (const float*)d_in[15]; const float* g1as  = (const float*)d_in[16];
    const float* g1ad  = (const float*)d_in[17]; const float* g1b   = (const float*)d_in[18];
    const float* g2W   = (const float*)d_in[19]; const float* g2as  = (const float*)d_in[20];
    const float* g2ad  = (const float*)d_in[21]; const float* g2b   = (const float*)d_in[22];
    const float* Wo1   = (const float*)d_in[23]; const float* bo1   = (const float*)d_in[24];
    const float* Wo2   = (const float*)d_in[25]; const float* bo2   = (const float*)d_in[26];
    float* out = (float*)d_out;

    float *px, *ph, *pz;
    cudaGetSymbolAddress((void**)&px, g_x);
    cudaGetSymbolAddress((void**)&ph, g_h);
    cudaGetSymbolAddress((void**)&pz, g_z);

    // CSR build (shared by both GAT layers)
    k_init_deg<<<(NN + 255) / 256, 256>>>();
    k_count<<<(EE + 255) / 256, 256>>>(ei);
    k_scan1<<<98, 1024>>>();
    k_scan2<<<1, 128>>>();
    k_scan3<<<98, 1024>>>();
    k_fill<<<(EE + NN + 255) / 256, 256>>>(ei);

    // feature encoding -> g_x [N,128]
    k_small<<<(NN * 32 + 255) / 256, 256>>>(np_, cp, W_np, b_np, W_cp, b_cp);
    k_gemm_enc<<<(NN + 255) / 256, 256>>>(des, 768, W_des, b_des, px, 0, NN, 768);
    k_gemm_enc<<<(NN + 255) / 256, 256>>>(tw,  768, W_tw,  b_tw,  px, 32, NN, 768);

    // input linear
    k_gemm128<<<(NN + 127) / 128, 256>>>(px, W_in, b_in, ph, NN, 1);

    // GAT layer 1 (H=4, C=32)
    k_gemm128<<<(NN + 127) / 128, 256>>>(ph, g1W, nullptr, pz, NN, 0);
    k_al<<<(NN + 7) / 8, 256>>>(pz, g1as, g1ad, NN, 4);
    k_gat<<<(NN + 7) / 8, 256>>>(pz, g1b, px, NN, 4);

    // GAT layer 2 (H=1, C=128)
    k_gemm128<<<(NN + 127) / 128, 256>>>(px, g2W, nullptr, ph, NN, 0);
    k_al<<<(NN + 7) / 8, 256>>>(ph, g2as, g2ad, NN, 1);
    k_gat<<<(NN + 7) / 8, 256>>>(ph, g2b, pz, NN, 1);

    // output head
    k_gemm128<<<(NN + 127) / 128, 256>>>(pz, Wo1, bo1, px, NN, 1);
    k_out<<<(NN + 7) / 8, 256>>>(px, Wo2, bo2, out, NN);
}

// round 3
// speedup vs baseline: 1.1317x; 1.1317x over previous
#include <cuda_runtime.h>

#define NN 100000
#define EE 1600000

typedef unsigned long long ull;

// ---------------- device scratch ----------------
__device__ float g_x[NN * 128];
__device__ float g_h[NN * 128];
__device__ float g_z[NN * 128];
__device__ float g_als[NN * 4];
__device__ float g_ald[NN * 4];
__device__ int   g_deg[NN];
__device__ int   g_ptr[NN + 1];
__device__ int   g_pos[NN];
__device__ int   g_csrc[EE + NN];
__device__ int   g_part[128];
__device__ int   g_partex[128];

__device__ __forceinline__ float lrelu(float v, float s) { return v > 0.f ? v : s * v; }

// ---- packed f32x2 helpers (Blackwell FFMA2 path, fp32-exact) ----
__device__ __forceinline__ void fma2(ull& d, ull a, ull b) {
    asm("fma.rn.f32x2 %0, %1, %2, %0;" : "+l"(d) : "l"(a), "l"(b));
}
__device__ __forceinline__ ull dup2(float x) {
    ull r; asm("mov.b64 %0, {%1, %1};" : "=l"(r) : "f"(x)); return r;
}
__device__ __forceinline__ void unpack2(ull v, float& lo, float& hi) {
    asm("mov.b64 {%0, %1}, %2;" : "=f"(lo), "=f"(hi) : "l"(v));
}

// ---------------- CSR build (dst-major), shared by both GAT layers ----------------
__global__ void k_init_deg() {
    int i = blockIdx.x * blockDim.x + threadIdx.x;
    if (i < NN) g_deg[i] = 1;  // self loop
}

__global__ void k_count(const int* __restrict__ ei) {
    int e = blockIdx.x * blockDim.x + threadIdx.x;
    if (e < EE) atomicAdd(&g_deg[ei[EE + e]], 1);
}

__global__ void k_scan1() {
    __shared__ int sm[1024];
    int t = threadIdx.x;
    int i = blockIdx.x * 1024 + t;
    int v = (i < NN) ? g_deg[i] : 0;
    sm[t] = v; __syncthreads();
    for (int off = 1; off < 1024; off <<= 1) {
        int x = (t >= off) ? sm[t - off] : 0;
        __syncthreads();
        sm[t] += x; __syncthreads();
    }
    if (i < NN) g_ptr[i + 1] = sm[t];
    if (t == 1023) g_part[blockIdx.x] = sm[t];
}

__global__ void k_scan2() {
    __shared__ int sm[128];
    int t = threadIdx.x;
    int v = (t < 98) ? g_part[t] : 0;
    sm[t] = v; __syncthreads();
    for (int off = 1; off < 128; off <<= 1) {
        int x = (t >= off) ? sm[t - off] : 0;
        __syncthreads();
        sm[t] += x; __syncthreads();
    }
    if (t < 98) g_partex[t] = sm[t] - v;
}

__global__ void k_scan3() {
    int t = threadIdx.x;
    int i = blockIdx.x * 1024 + t;
    if (i < NN) {
        int val = g_ptr[i + 1] + g_partex[blockIdx.x];
        g_ptr[i + 1] = val;
        g_pos[i] = val - g_deg[i];
        if (i == 0) g_ptr[0] = 0;
    }
}

__global__ void k_fill(const int* __restrict__ ei) {
    int idx = blockIdx.x * blockDim.x + threadIdx.x;
    if (idx < EE + NN) {
        int s, d;
        if (idx < EE) { s = ei[idx]; d = ei[EE + idx]; }
        else          { s = idx - EE; d = s; }
        int p = atomicAdd(&g_pos[d], 1);
        g_csrc[p] = s;
    }
}

// ---------------- GEMM: A[n,128] @ B[128,128] (+bias, optional leaky) ----------------
// 256 thr, tile 128x128, K chunk 32. Thread tile 8x8, accumulators packed f32x2
// over ROW pairs so the A operand is a direct 64-bit LDS from the transposed tile.
__global__ __launch_bounds__(256) void k_gemm128(
    const float* __restrict__ A, const float* __restrict__ B,
    const float* __restrict__ bias, float* __restrict__ C, int n, int doLeaky)
{
    __shared__ float As[32][132];
    __shared__ float Bs[32][132];
    int tid = threadIdx.x;
    int m0 = blockIdx.x * 128;
    int tr = tid >> 4, tc = tid & 15;
    // acc2[ci*4 + rp]: ci = col index 0..7, rp = row-pair 0..3
    ull acc2[32];
#pragma unroll
    for (int i = 0; i < 32; i++) acc2[i] = 0ull;

    for (int kc = 0; kc < 128; kc += 32) {
#pragma unroll
        for (int i = 0; i < 4; i++) {            // A tile 128x32 (transposed)
            int idx = i * 256 + tid;
            int r = idx >> 3, kq = idx & 7;
            float4 f = make_float4(0.f, 0.f, 0.f, 0.f);
            if (m0 + r < n) f = *(const float4*)&A[(size_t)(m0 + r) * 128 + kc + kq * 4];
            As[kq * 4 + 0][r] = f.x; As[kq * 4 + 1][r] = f.y;
            As[kq * 4 + 2][r] = f.z; As[kq * 4 + 3][r] = f.w;
        }
#pragma unroll
        for (int i = 0; i < 4; i++) {            // B tile 32x128
            int idx = i * 256 + tid;
            int k = idx >> 5, cq = idx & 31;
            float4 f = *(const float4*)&B[(kc + k) * 128 + cq * 4];
            *(float4*)&Bs[k][cq * 4] = f;
        }
        __syncthreads();
#pragma unroll
        for (int k = 0; k < 32; k++) {
            ull ap[4];
            ap[0] = *(const ull*)&As[k][tr * 4];
            ap[1] = *(const ull*)&As[k][tr * 4 + 2];
            ap[2] = *(const ull*)&As[k][64 + tr * 4];
            ap[3] = *(const ull*)&As[k][64 + tr * 4 + 2];
            float4 b0 = *(const float4*)&Bs[k][tc * 4];
            float4 b1 = *(const float4*)&Bs[k][64 + tc * 4];
            ull bd[8];
            bd[0] = dup2(b0.x); bd[1] = dup2(b0.y); bd[2] = dup2(b0.z); bd[3] = dup2(b0.w);
            bd[4] = dup2(b1.x); bd[5] = dup2(b1.y); bd[6] = dup2(b1.z); bd[7] = dup2(b1.w);
#pragma unroll
            for (int ci = 0; ci < 8; ci++)
#pragma unroll
                for (int rp = 0; rp < 4; rp++)
                    fma2(acc2[ci * 4 + rp], ap[rp], bd[ci]);
        }
        __syncthreads();
    }

    float bb[8];
#pragma unroll
    for (int ci = 0; ci < 8; ci++) {
        int c = (ci < 4) ? tc * 4 + ci : 64 + tc * 4 + (ci - 4);
        bb[ci] = bias ? bias[c] : 0.f;
    }
    // unpack: row-pair rp covers rows {base, base+1}
#pragma unroll
    for (int rp = 0; rp < 4; rp++) {
        int rbase = (rp < 2) ? tr * 4 + rp * 2 : 64 + tr * 4 + (rp - 2) * 2;
#pragma unroll
        for (int half = 0; half < 2; half++) {
            int r = rbase + half;
            if (m0 + r < n) {
                float4 o0, o1;
                float lo, hi, v;
#pragma unroll
                for (int ci = 0; ci < 8; ci++) {
                    unpack2(acc2[ci * 4 + rp], lo, hi);
                    v = (half ? hi : lo) + bb[ci];
                    v = doLeaky ? lrelu(v, 0.01f) : v;
                    ((float*)&o0)[ci < 4 ? ci : 0] = (ci < 4) ? v : ((float*)&o0)[0];
                    if (ci < 4) ((float*)&o0)[ci] = v; else ((float*)&o1)[ci - 4] = v;
                }
                *(float4*)&C[(size_t)(m0 + r) * 128 + tc * 4] = o0;
                *(float4*)&C[(size_t)(m0 + r) * 128 + 64 + tc * 4] = o1;
            }
        }
    }
}

// ---------------- GEMM: A[n,K] @ B[K,32] (+bias, leaky), C[:,colOff..+32) ----------------
// 256 thr, tile 256x32, K chunk 32. Thread tile 8x4 with f32x2 row-pair accumulators.
__global__ __launch_bounds__(256) void k_gemm_enc(
    const float* __restrict__ A, int lda,
    const float* __restrict__ B, const float* __restrict__ bias,
    float* __restrict__ C, int colOff, int n, int K)
{
    __shared__ float As[32][260];
    __shared__ float Bs[32][36];
    int tid = threadIdx.x;
    int m0 = blockIdx.x * 256;
    int tr = tid >> 3, tc = tid & 7;
    ull acc2[16];   // [ci*4 + rp]
#pragma unroll
    for (int i = 0; i < 16; i++) acc2[i] = 0ull;

    for (int kc = 0; kc < K; kc += 32) {
#pragma unroll
        for (int i = 0; i < 8; i++) {            // A tile 256x32 (transposed)
            int idx = i * 256 + tid;
            int r = idx >> 3, kq = idx & 7;
            float4 f = make_float4(0.f, 0.f, 0.f, 0.f);
            if (m0 + r < n) f = *(const float4*)&A[(size_t)(m0 + r) * lda + kc + kq * 4];
            As[kq * 4 + 0][r] = f.x; As[kq * 4 + 1][r] = f.y;
            As[kq * 4 + 2][r] = f.z; As[kq * 4 + 3][r] = f.w;
        }
        {                                         // B tile 32x32
            int k = tid >> 3, cq = tid & 7;
            float4 f = *(const float4*)&B[(kc + k) * 32 + cq * 4];
            *(float4*)&Bs[k][cq * 4] = f;
        }
        __syncthreads();
#pragma unroll
        for (int k = 0; k < 32; k++) {
            ull ap[4];
            ap[0] = *(const ull*)&As[k][tr * 4];
            ap[1] = *(const ull*)&As[k][tr * 4 + 2];
            ap[2] = *(const ull*)&As[k][128 + tr * 4];
            ap[3] = *(const ull*)&As[k][128 + tr * 4 + 2];
            float4 b = *(const float4*)&Bs[k][tc * 4];
            ull bd[4];
            bd[0] = dup2(b.x); bd[1] = dup2(b.y); bd[2] = dup2(b.z); bd[3] = dup2(b.w);
#pragma unroll
            for (int ci = 0; ci < 4; ci++)
#pragma unroll
                for (int rp = 0; rp < 4; rp++)
                    fma2(acc2[ci * 4 + rp], ap[rp], bd[ci]);
        }
        __syncthreads();
    }

    float bb[4];
#pragma unroll
    for (int ci = 0; ci < 4; ci++) bb[ci] = bias[tc * 4 + ci];
#pragma unroll
    for (int rp = 0; rp < 4; rp++) {
        int rbase = (rp < 2) ? tr * 4 + rp * 2 : 128 + tr * 4 + (rp - 2) * 2;
#pragma unroll
        for (int half = 0; half < 2; half++) {
            int r = rbase + half;
            if (m0 + r < n) {
                float4 o;
                float lo, hi;
#pragma unroll
                for (int ci = 0; ci < 4; ci++) {
                    unpack2(acc2[ci * 4 + rp], lo, hi);
                    ((float*)&o)[ci] = lrelu((half ? hi : lo) + bb[ci], 0.01f);
                }
                *(float4*)&C[(size_t)(m0 + r) * 128 + colOff + tc * 4] = o;
            }
        }
    }
}

// ---------------- tiny encoders (num_prop 5->32, cat_prop 3->32) ----------------
__global__ void k_small(const float* __restrict__ np_, const float* __restrict__ cp,
                        const float* __restrict__ Wnp, const float* __restrict__ bnp,
                        const float* __restrict__ Wcp, const float* __restrict__ bcp)
{
    int g = blockIdx.x * blockDim.x + threadIdx.x;
    int nID = g >> 5, c = g & 31;
    if (nID >= NN) return;
    float s = bnp[c];
#pragma unroll
    for (int k = 0; k < 5; k++) s += __ldg(&np_[nID * 5 + k]) * Wnp[k * 32 + c];
    g_x[(size_t)nID * 128 + 64 + c] = lrelu(s, 0.01f);
    float s2 = bcp[c];
#pragma unroll
    for (int k = 0; k < 3; k++) s2 += __ldg(&cp[nID * 3 + k]) * Wcp[k * 32 + c];
    g_x[(size_t)nID * 128 + 96 + c] = lrelu(s2, 0.01f);
}

// ---------------- per-node attention logit halves: als/ald ----------------
__global__ void k_al(const float* __restrict__ h, const float* __restrict__ asrc,
                     const float* __restrict__ adst, int n, int H)
{
    int w = (blockIdx.x * blockDim.x + threadIdx.x) >> 5;
    int lane = threadIdx.x & 31;
    if (w >= n) return;
    float ps[4], pd[4];
#pragma unroll
    for (int q = 0; q < 4; q++) {
        float hv = h[(size_t)w * 128 + q * 32 + lane];
        ps[q] = hv * asrc[q * 32 + lane];
        pd[q] = hv * adst[q * 32 + lane];
    }
    if (H == 1) { ps[0] += ps[1] + ps[2] + ps[3]; pd[0] += pd[1] + pd[2] + pd[3]; }
    int QQ = (H == 4) ? 4 : 1;
    for (int q = 0; q < QQ; q++) {
        float s1 = ps[q], s2 = pd[q];
        for (int off = 16; off; off >>= 1) {
            s1 += __shfl_xor_sync(0xffffffffu, s1, off);
            s2 += __shfl_xor_sync(0xffffffffu, s2, off);
        }
        if (lane == 0) { g_als[(size_t)w * H + q] = s1; g_ald[(size_t)w * H + q] = s2; }
    }
}

// ---------------- GAT aggregation: warp per node, CSR gather, two-sweep softmax ----------------
__global__ void k_gat(const float* __restrict__ h, const float* __restrict__ bias,
                      float* __restrict__ out, int n, int H)
{
    int w = (blockIdx.x * blockDim.x + threadIdx.x) >> 5;
    int lane = threadIdx.x & 31;
    if (w >= n) return;
    int beg = g_ptr[w], end = g_ptr[w + 1];
    float aldv = (lane < H) ? g_ald[(size_t)w * H + lane] : 0.f;

    float mx = -1e30f;
    for (int e = beg; e < end; e++) {
        int src = __ldg(&g_csrc[e]);
        if (lane < H) {
            float v = g_als[(size_t)src * H + lane] + aldv;
            v = v > 0.f ? v : 0.2f * v;
            mx = fmaxf(mx, v);
        }
    }

    float s[4] = {0.f, 0.f, 0.f, 0.f}, acc[4] = {0.f, 0.f, 0.f, 0.f};
    for (int e = beg; e < end; e++) {
        int src = __ldg(&g_csrc[e]);
        float wv = 0.f;
        if (lane < H) {
            float v = g_als[(size_t)src * H + lane] + aldv;
            v = v > 0.f ? v : 0.2f * v;
            wv = __expf(v - mx);
        }
#pragma unroll
        for (int q = 0; q < 4; q++) {
            int hq = (H == 4) ? q : 0;
            float wq = __shfl_sync(0xffffffffu, wv, hq);
            float hv = __ldg(&h[(size_t)src * 128 + q * 32 + lane]);
            s[q] += wq;
            acc[q] += wq * hv;
        }
    }
#pragma unroll
    for (int q = 0; q < 4; q++) {
        int ch = q * 32 + lane;
        out[(size_t)w * 128 + ch] = acc[q] / (s[q] + 1e-16f) + bias[ch];
    }
}

// ---------------- output head: z[n,128] @ W_o2[128,2] + b ----------------
__global__ void k_out(const float* __restrict__ z, const float* __restrict__ W,
                      const float* __restrict__ b, float* __restrict__ out, int n)
{
    int w = (blockIdx.x * blockDim.x + threadIdx.x) >> 5;
    int lane = threadIdx.x & 31;
    if (w >= n) return;
    float p0 = 0.f, p1 = 0.f;
#pragma unroll
    for (int q = 0; q < 4; q++) {
        int ch = q * 32 + lane;
        float zv = z[(size_t)w * 128 + ch];
        p0 += zv * W[ch * 2];
        p1 += zv * W[ch * 2 + 1];
    }
    for (int off = 16; off; off >>= 1) {
        p0 += __shfl_xor_sync(0xffffffffu, p0, off);
        p1 += __shfl_xor_sync(0xffffffffu, p1, off);
    }
    if (lane == 0) { out[2 * w] = p0 + b[0]; out[2 * w + 1] = p1 + b[1]; }
}

// ---------------- launch ----------------
extern "C" void kernel_launch(void* const* d_in, const int* in_sizes, int n_in,
                              void* d_out, int out_size)
{
    const float* des  = (const float*)d_in[0];
    const float* tw   = (const float*)d_in[1];
    const float* np_  = (const float*)d_in[2];
    const float* cp   = (const float*)d_in[3];
    const int*   ei   = (const int*)d_in[4];
    const float* W_des = (const float*)d_in[5];  const float* b_des = (const float*)d_in[6];
    const float* W_tw  = (const float*)d_in[7];  const float* b_tw  = (const float*)d_in[8];
    const float* W_np  = (const float*)d_in[9];  const float* b_np  = (const float*)d_in[10];
    const float* W_cp  = (const float*)d_in[11]; const float* b_cp  = (const float*)d_in[12];
    const float* W_in  = (const float*)d_in[13]; const float* b_in  = (const float*)d_in[14];
    const float* g1W   = (const float*)d_in[15]; const float* g1as  = (const float*)d_in[16];
    const float* g1ad  = (const float*)d_in[17]; const float* g1b   = (const float*)d_in[18];
    const float* g2W   = (const float*)d_in[19]; const float* g2as  = (const float*)d_in[20];
    const float* g2ad  = (const float*)d_in[21]; const float* g2b   = (const float*)d_in[22];
    const float* Wo1   = (const float*)d_in[23]; const float* bo1   = (const float*)d_in[24];
    const float* Wo2   = (const float*)d_in[25]; const float* bo2   = (const float*)d_in[26];
    float* out = (float*)d_out;

    float *px, *ph, *pz;
    cudaGetSymbolAddress((void**)&px, g_x);
    cudaGetSymbolAddress((void**)&ph, g_h);
    cudaGetSymbolAddress((void**)&pz, g_z);

    // CSR build (shared by both GAT layers)
    k_init_deg<<<(NN + 255) / 256, 256>>>();
    k_count<<<(EE + 255) / 256, 256>>>(ei);
    k_scan1<<<98, 1024>>>();
    k_scan2<<<1, 128>>>();
    k_scan3<<<98, 1024>>>();
    k_fill<<<(EE + NN + 255) / 256, 256>>>(ei);

    // feature encoding -> g_x [N,128]
    k_small<<<(NN * 32 + 255) / 256, 256>>>(np_, cp, W_np, b_np, W_cp, b_cp);
    k_gemm_enc<<<(NN + 255) / 256, 256>>>(des, 768, W_des, b_des, px, 0, NN, 768);
    k_gemm_enc<<<(NN + 255) / 256, 256>>>(tw,  768, W_tw,  b_tw,  px, 32, NN, 768);

    // input linear
    k_gemm128<<<(NN + 127) / 128, 256>>>(px, W_in, b_in, ph, NN, 1);

    // GAT layer 1 (H=4, C=32)
    k_gemm128<<<(NN + 127) / 128, 256>>>(ph, g1W, nullptr, pz, NN, 0);
    k_al<<<(NN + 7) / 8, 256>>>(pz, g1as, g1ad, NN, 4);
    k_gat<<<(NN + 7) / 8, 256>>>(pz, g1b, px, NN, 4);

    // GAT layer 2 (H=1, C=128)
    k_gemm128<<<(NN + 127) / 128, 256>>>(px, g2W, nullptr, ph, NN, 0);
    k_al<<<(NN + 7) / 8, 256>>>(ph, g2as, g2ad, NN, 1);
    k_gat<<<(NN + 7) / 8, 256>>>(ph, g2b, pz, NN, 1);

    // output head
    k_gemm128<<<(NN + 127) / 128, 256>>>(pz, Wo1, bo1, px, NN, 1);
    k_out<<<(NN + 7) / 8, 256>>>(px, Wo2, bo2, out, NN);
}